// round 5
// baseline (speedup 1.0000x reference)
#include <cuda_runtime.h>
#include <math.h>

// Problem constants
#define BATCH  4
#define SLQ    2048
#define SLK    2048
#define DMODEL 768
#define NHEAD  12
#define DHEAD  64
#define MROWS  (BATCH * SLQ)   // 8192

// ---------------------------------------------------------------------------
// Scratch (device globals; no allocation allowed)
// ---------------------------------------------------------------------------
__device__ float g_q  [(size_t)MROWS * DMODEL];
__device__ float g_k  [(size_t)BATCH * SLK * DMODEL];
__device__ float g_v  [(size_t)BATCH * SLK * DMODEL];
__device__ float g_att[(size_t)MROWS * DMODEL];
__device__ float g_ao [(size_t)MROWS * DMODEL];
__device__ float g_f1 [(size_t)MROWS * DMODEL];
__device__ float g_y  [(size_t)MROWS * DMODEL];
__device__ int   g_valid[BATCH];

// ---------------------------------------------------------------------------
// valid_lens[b] = count of nonzero mask entries in row b
// ---------------------------------------------------------------------------
__global__ void valid_kernel(const int* __restrict__ mask) {
    __shared__ int red[256];
    int b = blockIdx.x;
    int cnt = 0;
    for (int i = threadIdx.x; i < SLK; i += 256)
        cnt += (mask[b * SLK + i] != 0) ? 1 : 0;
    red[threadIdx.x] = cnt;
    __syncthreads();
    for (int s = 128; s > 0; s >>= 1) {
        if (threadIdx.x < s) red[threadIdx.x] += red[threadIdx.x + s];
        __syncthreads();
    }
    if (threadIdx.x == 0) g_valid[b] = red[0];
}

// ---------------------------------------------------------------------------
// SGEMM: C[M,N] = A[M,K] @ B[K,N]  (M=8192, N=K=768 fixed)
// 128x128 tile, BK=8, 256 threads, 8x8 micro-tile.
// ASEL: 0=external param, 1=g_att, 2=g_ao, 3=g_f1
// CSEL: 0=g_q 1=g_k 2=g_v 3=g_ao 4=g_f1 5=g_y
// MODE: 0=plain, 1=+bias,ReLU, 2=+bias,+residual(g_ao)
// ---------------------------------------------------------------------------
#define GK DMODEL
#define GN DMODEL

template<int ASEL, int CSEL, int MODE>
__global__ __launch_bounds__(256, 2)
void sgemm_kernel(const float* __restrict__ Aext,
                  const float* __restrict__ Bm,
                  const float* __restrict__ bias)
{
    const float* A = (ASEL == 0) ? Aext : (ASEL == 1) ? g_att
                   : (ASEL == 2) ? g_ao : g_f1;
    float* C = (CSEL == 0) ? g_q : (CSEL == 1) ? g_k : (CSEL == 2) ? g_v
             : (CSEL == 3) ? g_ao : (CSEL == 4) ? g_f1 : g_y;

    __shared__ float As[8][132];   // transposed A tile, padded
    __shared__ float Bs[8][128];

    const int bx = blockIdx.x;     // N tile (0..5)
    const int by = blockIdx.y;     // M tile (0..63)
    const int tid = threadIdx.x;
    const int tx = tid & 15;
    const int ty = tid >> 4;

    float acc[8][8];
#pragma unroll
    for (int i = 0; i < 8; i++)
#pragma unroll
        for (int j = 0; j < 8; j++) acc[i][j] = 0.0f;

    const int a_row = tid >> 1;          // 0..127
    const int a_col = (tid & 1) * 4;     // 0 or 4
    const int b_row = tid >> 5;          // 0..7
    const int b_col = (tid & 31) * 4;    // 0..124

    const float* Ap = A + (size_t)(by * 128) * GK;
    const float* Bp = Bm + bx * 128;

    for (int k0 = 0; k0 < GK; k0 += 8) {
        float4 av = *(const float4*)(Ap + (size_t)a_row * GK + k0 + a_col);
        As[a_col + 0][a_row] = av.x;
        As[a_col + 1][a_row] = av.y;
        As[a_col + 2][a_row] = av.z;
        As[a_col + 3][a_row] = av.w;
        *(float4*)&Bs[b_row][b_col] =
            *(const float4*)(Bp + (size_t)(k0 + b_row) * GN + b_col);
        __syncthreads();

#pragma unroll
        for (int kk = 0; kk < 8; kk++) {
            float ar[8], br[8];
            *(float4*)&ar[0] = *(const float4*)&As[kk][ty * 8];
            *(float4*)&ar[4] = *(const float4*)&As[kk][ty * 8 + 4];
            *(float4*)&br[0] = *(const float4*)&Bs[kk][tx * 8];
            *(float4*)&br[4] = *(const float4*)&Bs[kk][tx * 8 + 4];
#pragma unroll
            for (int i = 0; i < 8; i++)
#pragma unroll
                for (int j = 0; j < 8; j++)
                    acc[i][j] += ar[i] * br[j];
        }
        __syncthreads();
    }

    const int row0 = by * 128 + ty * 8;
    const int col0 = bx * 128 + tx * 8;
#pragma unroll
    for (int i = 0; i < 8; i++) {
        float* crow = C + (size_t)(row0 + i) * GN + col0;
        const float* rrow = g_ao + (size_t)(row0 + i) * GN + col0;
        float v[8];
#pragma unroll
        for (int j = 0; j < 8; j++) {
            v[j] = acc[i][j];
            if (MODE >= 1) v[j] += bias[col0 + j];
            if (MODE == 1) v[j] = fmaxf(v[j], 0.0f);
            if (MODE == 2) v[j] += rrow[j];
        }
        *(float4*)&crow[0] = make_float4(v[0], v[1], v[2], v[3]);
        *(float4*)&crow[4] = make_float4(v[4], v[5], v[6], v[7]);
    }
}

// ---------------------------------------------------------------------------
// Flash attention: per block one (b, h, 64-row q tile).
// Online softmax in registers (row group = 16 contiguous lanes).
// Skips K tiles entirely beyond valid_len (exact: exp(-1e6 - m) == 0 in fp32).
// ---------------------------------------------------------------------------
#define BQ  64
#define BKT 64
#define PAD 68
#define ATTN_SMEM (4 * 64 * PAD * sizeof(float))   // 69632 B

__global__ __launch_bounds__(256)
void attn_kernel() {
    extern __shared__ float sm[];
    float* Qs = sm;                 // [d][r]
    float* Ks = Qs + 64 * PAD;      // [d][c]
    float* Vs = Ks + 64 * PAD;      // [c][j]
    float* Ps = Vs + 64 * PAD;      // [c][r]

    const int qt = blockIdx.x;
    const int h  = blockIdx.y;
    const int b  = blockIdx.z;
    const int tid = threadIdx.x;
    const int tx = tid & 15;
    const int ty = tid >> 4;
    const int r0 = ty * 4;
    const int c0 = tx * 4;

    const int valid = g_valid[b];
    const int nkt = (valid > 0) ? ((valid + BKT - 1) / BKT) : (SLK / BKT);

    const float* Qb = g_q + ((size_t)b * SLQ + qt * BQ) * DMODEL + h * DHEAD;
    const float* Kb = g_k + (size_t)b * SLK * DMODEL + h * DHEAD;
    const float* Vb = g_v + (size_t)b * SLK * DMODEL + h * DHEAD;

    // load Q tile (transposed: Qs[d][r])
#pragma unroll
    for (int it = 0; it < (BQ * DHEAD) / 256; it++) {
        int idx = tid + it * 256;
        int r = idx >> 6, d = idx & 63;
        Qs[d * PAD + r] = Qb[(size_t)r * DMODEL + d];
    }

    float m[4], l[4], o[4][4];
#pragma unroll
    for (int i = 0; i < 4; i++) {
        m[i] = -1e30f; l[i] = 0.0f;
#pragma unroll
        for (int j = 0; j < 4; j++) o[i][j] = 0.0f;
    }

    for (int kt = 0; kt < nkt; kt++) {
        __syncthreads();   // previous iteration's PV reads done
#pragma unroll
        for (int it = 0; it < (BKT * DHEAD) / 256; it++) {
            int idx = tid + it * 256;
            int c = idx >> 6, d = idx & 63;
            float kvk = Kb[(size_t)(kt * BKT + c) * DMODEL + d];
            float kvv = Vb[(size_t)(kt * BKT + c) * DMODEL + d];
            Ks[d * PAD + c] = kvk;
            Vs[c * PAD + d] = kvv;
        }
        __syncthreads();

        // S = Q K^T
        float s[4][4];
#pragma unroll
        for (int i = 0; i < 4; i++)
#pragma unroll
            for (int j = 0; j < 4; j++) s[i][j] = 0.0f;

#pragma unroll 8
        for (int d = 0; d < 64; d++) {
            float4 a  = *(const float4*)&Qs[d * PAD + r0];
            float4 bb = *(const float4*)&Ks[d * PAD + c0];
            float av[4] = {a.x, a.y, a.z, a.w};
            float bv[4] = {bb.x, bb.y, bb.z, bb.w};
#pragma unroll
            for (int i = 0; i < 4; i++)
#pragma unroll
                for (int j = 0; j < 4; j++)
                    s[i][j] += av[i] * bv[j];
        }

        const float scale = 0.125f;   // 1/sqrt(64)
        const int kg0 = kt * BKT + c0;
#pragma unroll
        for (int i = 0; i < 4; i++)
#pragma unroll
            for (int j = 0; j < 4; j++) {
                float v = s[i][j] * scale;
                if (kg0 + j >= valid) v = -1e6f;
                s[i][j] = v;
            }

        // online softmax per row (rows live in 16 contiguous lanes)
#pragma unroll
        for (int i = 0; i < 4; i++) {
            float tm = fmaxf(fmaxf(s[i][0], s[i][1]), fmaxf(s[i][2], s[i][3]));
#pragma unroll
            for (int off = 1; off < 16; off <<= 1)
                tm = fmaxf(tm, __shfl_xor_sync(0xffffffffu, tm, off));
            float mn = fmaxf(m[i], tm);
            float corr = __expf(m[i] - mn);
            float p[4];
            float ts = 0.0f;
#pragma unroll
            for (int j = 0; j < 4; j++) { p[j] = __expf(s[i][j] - mn); ts += p[j]; }
#pragma unroll
            for (int off = 1; off < 16; off <<= 1)
                ts += __shfl_xor_sync(0xffffffffu, ts, off);
            l[i] = l[i] * corr + ts;
            m[i] = mn;
#pragma unroll
            for (int j = 0; j < 4; j++) o[i][j] *= corr;
#pragma unroll
            for (int j = 0; j < 4; j++) Ps[(c0 + j) * PAD + (r0 + i)] = p[j];
        }
        __syncthreads();

        // O += P V
#pragma unroll 8
        for (int c = 0; c < 64; c++) {
            float4 pv = *(const float4*)&Ps[c * PAD + r0];
            float4 vv = *(const float4*)&Vs[c * PAD + c0];
            float pa[4] = {pv.x, pv.y, pv.z, pv.w};
            float vb2[4] = {vv.x, vv.y, vv.z, vv.w};
#pragma unroll
            for (int i = 0; i < 4; i++)
#pragma unroll
                for (int j = 0; j < 4; j++)
                    o[i][j] += pa[i] * vb2[j];
        }
    }

    float* Ob = g_att + ((size_t)b * SLQ + qt * BQ) * DMODEL + h * DHEAD;
#pragma unroll
    for (int i = 0; i < 4; i++) {
        float inv = 1.0f / l[i];
#pragma unroll
        for (int j = 0; j < 4; j++)
            Ob[(size_t)(r0 + i) * DMODEL + c0 + j] = o[i][j] * inv;
    }
}

// ---------------------------------------------------------------------------
// LayerNorm over g_y rows -> out
// ---------------------------------------------------------------------------
__global__ __launch_bounds__(256)
void ln_kernel(const float* __restrict__ gamma,
               const float* __restrict__ beta,
               float* __restrict__ out)
{
    __shared__ float rs[256], rs2[256];
    const int row = blockIdx.x;
    const float* y = g_y + (size_t)row * DMODEL;
    float v[3], s = 0.0f, s2 = 0.0f;
#pragma unroll
    for (int t = 0; t < 3; t++) {
        v[t] = y[threadIdx.x + t * 256];
        s += v[t]; s2 += v[t] * v[t];
    }
    rs[threadIdx.x] = s; rs2[threadIdx.x] = s2;
    __syncthreads();
    for (int st = 128; st > 0; st >>= 1) {
        if (threadIdx.x < st) {
            rs[threadIdx.x]  += rs[threadIdx.x + st];
            rs2[threadIdx.x] += rs2[threadIdx.x + st];
        }
        __syncthreads();
    }
    const float mean = rs[0] * (1.0f / DMODEL);
    const float var  = rs2[0] * (1.0f / DMODEL) - mean * mean;
    const float inv  = rsqrtf(var + 1e-5f);
#pragma unroll
    for (int t = 0; t < 3; t++) {
        int col = threadIdx.x + t * 256;
        out[(size_t)row * DMODEL + col] = (v[t] - mean) * inv * gamma[col] + beta[col];
    }
}

// ---------------------------------------------------------------------------
// Launch
// ---------------------------------------------------------------------------
extern "C" void kernel_launch(void* const* d_in, const int* in_sizes, int n_in,
                              void* d_out, int out_size)
{
    (void)in_sizes; (void)n_in; (void)out_size;
    const float* queries = (const float*)d_in[0];
    const float* keys    = (const float*)d_in[1];
    const float* values  = (const float*)d_in[2];
    const int*   mask    = (const int*)  d_in[3];
    const float* Wq = (const float*)d_in[4];
    const float* Wk = (const float*)d_in[5];
    const float* Wv = (const float*)d_in[6];
    const float* Wo = (const float*)d_in[7];
    const float* W1 = (const float*)d_in[8];
    const float* b1 = (const float*)d_in[9];
    const float* W2 = (const float*)d_in[10];
    const float* b2 = (const float*)d_in[11];
    const float* lg = (const float*)d_in[12];
    const float* lb = (const float*)d_in[13];
    float* out = (float*)d_out;

    valid_kernel<<<BATCH, 256>>>(mask);

    dim3 ggrid(GN / 128, MROWS / 128);   // (6, 64)
    sgemm_kernel<0, 0, 0><<<ggrid, 256>>>(queries, Wq, nullptr);
    sgemm_kernel<0, 1, 0><<<ggrid, 256>>>(keys,    Wk, nullptr);
    sgemm_kernel<0, 2, 0><<<ggrid, 256>>>(values,  Wv, nullptr);

    cudaFuncSetAttribute(attn_kernel,
                         cudaFuncAttributeMaxDynamicSharedMemorySize,
                         (int)ATTN_SMEM);
    attn_kernel<<<dim3(SLQ / BQ, NHEAD, BATCH), 256, ATTN_SMEM>>>();

    sgemm_kernel<1, 3, 0><<<ggrid, 256>>>(nullptr, Wo, nullptr);  // att_out
    sgemm_kernel<2, 4, 1><<<ggrid, 256>>>(nullptr, W1, b1);       // relu(ffn1)
    sgemm_kernel<3, 5, 2><<<ggrid, 256>>>(nullptr, W2, b2);       // y = ffn2 + att_out

    ln_kernel<<<MROWS, 256>>>(lg, lb, out);
}

// round 6
// speedup vs baseline: 1.6687x; 1.6687x over previous
#include <cuda_runtime.h>
#include <math.h>

// Problem constants
#define BATCH  4
#define SLQ    2048
#define SLK    2048
#define DMODEL 768
#define NHEAD  12
#define DHEAD  64
#define MROWS  (BATCH * SLQ)   // 8192

// ---------------------------------------------------------------------------
// Scratch (device globals; no allocation allowed)
// ---------------------------------------------------------------------------
__device__ float g_q  [(size_t)MROWS * DMODEL];
__device__ float g_k  [(size_t)BATCH * SLK * DMODEL];
__device__ float g_v  [(size_t)BATCH * SLK * DMODEL];
__device__ float g_att[(size_t)MROWS * DMODEL];
__device__ float g_ao [(size_t)MROWS * DMODEL];
__device__ float g_f1 [(size_t)MROWS * DMODEL];
__device__ float g_y  [(size_t)MROWS * DMODEL];
__device__ int   g_valid[BATCH];

// ---------------------------------------------------------------------------
// valid_lens[b] = count of nonzero mask entries in row b
// ---------------------------------------------------------------------------
__global__ void valid_kernel(const int* __restrict__ mask) {
    __shared__ int red[256];
    int b = blockIdx.x;
    int cnt = 0;
    for (int i = threadIdx.x; i < SLK; i += 256)
        cnt += (mask[b * SLK + i] != 0) ? 1 : 0;
    red[threadIdx.x] = cnt;
    __syncthreads();
    for (int s = 128; s > 0; s >>= 1) {
        if (threadIdx.x < s) red[threadIdx.x] += red[threadIdx.x + s];
        __syncthreads();
    }
    if (threadIdx.x == 0) g_valid[b] = red[0];
}

// ---------------------------------------------------------------------------
// TF32 tensor-core GEMM: C[M,N] = A[M,K] @ B[K,N]  (M=8192, N=K=768)
// 128x128 block tile, BK=16 double-buffered, 8 warps, warp tile 32x64,
// mma.sync.aligned.m16n8k8.row.col.f32.tf32.tf32.f32, cvt.rna on smem store.
// ASEL: 0=external param, 1=g_att, 2=g_ao, 3=g_f1
// CSEL: 0=g_q 1=g_k 2=g_v 3=g_ao 4=g_f1 5=g_y
// MODE: 0=plain, 1=+bias,ReLU, 2=+bias,+residual(g_ao)
// ---------------------------------------------------------------------------
#define GK DMODEL
#define GN DMODEL
#define ASTRIDE 20    // 16 + 4 pad: 20*g mod 32 distinct groups -> conflict-free
#define BSTRIDE 136   // 128 + 8 pad: 136 mod 32 = 8 -> 8t+g conflict-free

__device__ __forceinline__ unsigned f2tf(float f) {
    unsigned u;
    asm("cvt.rna.tf32.f32 %0, %1;" : "=r"(u) : "f"(f));
    return u;
}

__device__ __forceinline__ void mma_tf32(float c[4],
                                         const unsigned a[4],
                                         const unsigned b[2]) {
    asm volatile(
        "mma.sync.aligned.m16n8k8.row.col.f32.tf32.tf32.f32 "
        "{%0,%1,%2,%3}, {%4,%5,%6,%7}, {%8,%9}, {%0,%1,%2,%3};"
        : "+f"(c[0]), "+f"(c[1]), "+f"(c[2]), "+f"(c[3])
        : "r"(a[0]), "r"(a[1]), "r"(a[2]), "r"(a[3]),
          "r"(b[0]), "r"(b[1]));
}

template<int ASEL, int CSEL, int MODE>
__global__ __launch_bounds__(256)
void tgemm_kernel(const float* __restrict__ Aext,
                  const float* __restrict__ Bm,
                  const float* __restrict__ bias)
{
    const float* A = (ASEL == 0) ? Aext : (ASEL == 1) ? g_att
                   : (ASEL == 2) ? g_ao : g_f1;
    float* C = (CSEL == 0) ? g_q : (CSEL == 1) ? g_k : (CSEL == 2) ? g_v
             : (CSEL == 3) ? g_ao : (CSEL == 4) ? g_f1 : g_y;

    __shared__ unsigned As[2][128 * ASTRIDE];   // [m][k] padded
    __shared__ unsigned Bs[2][16 * BSTRIDE];    // [k][n] padded

    const int bx = blockIdx.x;    // N tile (0..5)
    const int by = blockIdx.y;    // M tile (0..63)
    const int tid = threadIdx.x;
    const int warp = tid >> 5;
    const int lane = tid & 31;
    const int wm = warp >> 1;     // 0..3 (rows)
    const int wn = warp & 1;      // 0..1 (cols)
    const int g  = lane >> 2;     // 0..7
    const int t  = lane & 3;      // 0..3

    float acc[2][8][4];
#pragma unroll
    for (int mi = 0; mi < 2; mi++)
#pragma unroll
        for (int nj = 0; nj < 8; nj++)
#pragma unroll
            for (int q = 0; q < 4; q++) acc[mi][nj][q] = 0.0f;

    // gmem load mapping (per thread: 8 A floats + 8 B floats per BK tile)
    const int arow = tid >> 1;          // 0..127
    const int akc  = (tid & 1) * 8;     // 0 or 8
    const int bkr  = tid >> 4;          // 0..15
    const int bcol = (tid & 15) * 8;    // 0..120

    const float* Ag = A  + (size_t)(by * 128 + arow) * GK + akc;
    const float* Bg = Bm + (size_t)bkr * GN + bx * 128 + bcol;

    float4 pa0, pa1, pb0, pb1;

    // prologue: load tile 0
    pa0 = *(const float4*)(Ag);
    pa1 = *(const float4*)(Ag + 4);
    pb0 = *(const float4*)(Bg);
    pb1 = *(const float4*)(Bg + 4);
    {
        unsigned* as = &As[0][arow * ASTRIDE + akc];
        *(uint4*)as       = make_uint4(f2tf(pa0.x), f2tf(pa0.y), f2tf(pa0.z), f2tf(pa0.w));
        *(uint4*)(as + 4) = make_uint4(f2tf(pa1.x), f2tf(pa1.y), f2tf(pa1.z), f2tf(pa1.w));
        unsigned* bs = &Bs[0][bkr * BSTRIDE + bcol];
        *(uint4*)bs       = make_uint4(f2tf(pb0.x), f2tf(pb0.y), f2tf(pb0.z), f2tf(pb0.w));
        *(uint4*)(bs + 4) = make_uint4(f2tf(pb1.x), f2tf(pb1.y), f2tf(pb1.z), f2tf(pb1.w));
    }
    __syncthreads();

    const int NKT = GK / 16;   // 48
    int cur = 0;
#pragma unroll 1
    for (int kt = 0; kt < NKT; kt++) {
        if (kt + 1 < NKT) {
            const float* ag = Ag + (kt + 1) * 16;
            const float* bg = Bg + (size_t)(kt + 1) * 16 * GN;
            pa0 = *(const float4*)(ag);
            pa1 = *(const float4*)(ag + 4);
            pb0 = *(const float4*)(bg);
            pb1 = *(const float4*)(bg + 4);
        }

#pragma unroll
        for (int kk = 0; kk < 16; kk += 8) {
            unsigned af[2][4], bf[8][2];
#pragma unroll
            for (int mi = 0; mi < 2; mi++) {
                const int r = wm * 32 + mi * 16 + g;
                const unsigned* base = &As[cur][r * ASTRIDE + kk + t];
                af[mi][0] = base[0];
                af[mi][1] = base[8 * ASTRIDE];
                af[mi][2] = base[4];
                af[mi][3] = base[8 * ASTRIDE + 4];
            }
#pragma unroll
            for (int nj = 0; nj < 8; nj++) {
                const int c = wn * 64 + nj * 8 + g;
                bf[nj][0] = Bs[cur][(kk + t)     * BSTRIDE + c];
                bf[nj][1] = Bs[cur][(kk + t + 4) * BSTRIDE + c];
            }
#pragma unroll
            for (int mi = 0; mi < 2; mi++)
#pragma unroll
                for (int nj = 0; nj < 8; nj++)
                    mma_tf32(acc[mi][nj], af[mi], bf[nj]);
        }

        if (kt + 1 < NKT) {
            const int nxt = cur ^ 1;
            unsigned* as = &As[nxt][arow * ASTRIDE + akc];
            *(uint4*)as       = make_uint4(f2tf(pa0.x), f2tf(pa0.y), f2tf(pa0.z), f2tf(pa0.w));
            *(uint4*)(as + 4) = make_uint4(f2tf(pa1.x), f2tf(pa1.y), f2tf(pa1.z), f2tf(pa1.w));
            unsigned* bs = &Bs[nxt][bkr * BSTRIDE + bcol];
            *(uint4*)bs       = make_uint4(f2tf(pb0.x), f2tf(pb0.y), f2tf(pb0.z), f2tf(pb0.w));
            *(uint4*)(bs + 4) = make_uint4(f2tf(pb1.x), f2tf(pb1.y), f2tf(pb1.z), f2tf(pb1.w));
            __syncthreads();
            cur = nxt;
        }
    }

    // epilogue: c0,c1 at (r, c..c+1); c2,c3 at (r+8, c..c+1)
    const int row0 = by * 128 + wm * 32;
    const int col0 = bx * 128 + wn * 64;
#pragma unroll
    for (int mi = 0; mi < 2; mi++) {
#pragma unroll
        for (int nj = 0; nj < 8; nj++) {
            const int r = row0 + mi * 16 + g;
            const int c = col0 + nj * 8 + t * 2;
            float v0 = acc[mi][nj][0], v1 = acc[mi][nj][1];
            float v2 = acc[mi][nj][2], v3 = acc[mi][nj][3];
            if (MODE >= 1) {
                const float bb0 = bias[c], bb1 = bias[c + 1];
                v0 += bb0; v1 += bb1; v2 += bb0; v3 += bb1;
            }
            if (MODE == 1) {
                v0 = fmaxf(v0, 0.0f); v1 = fmaxf(v1, 0.0f);
                v2 = fmaxf(v2, 0.0f); v3 = fmaxf(v3, 0.0f);
            }
            if (MODE == 2) {
                const float* rr0 = g_ao + (size_t)r * GN + c;
                const float* rr1 = g_ao + (size_t)(r + 8) * GN + c;
                v0 += rr0[0]; v1 += rr0[1];
                v2 += rr1[0]; v3 += rr1[1];
            }
            *(float2*)(C + (size_t)r * GN + c)       = make_float2(v0, v1);
            *(float2*)(C + (size_t)(r + 8) * GN + c) = make_float2(v2, v3);
        }
    }
}

// ---------------------------------------------------------------------------
// Flash attention: per block one (b, h, 64-row q tile).
// Online softmax in registers (row group = 16 contiguous lanes).
// Skips K tiles entirely beyond valid_len (exact: exp(-1e6 - m) == 0 in fp32).
// ---------------------------------------------------------------------------
#define BQ  64
#define BKT 64
#define PAD 68
#define ATTN_SMEM (4 * 64 * PAD * sizeof(float))   // 69632 B

__global__ __launch_bounds__(256)
void attn_kernel() {
    extern __shared__ float sm[];
    float* Qs = sm;                 // [d][r]
    float* Ks = Qs + 64 * PAD;      // [d][c]
    float* Vs = Ks + 64 * PAD;      // [c][j]
    float* Ps = Vs + 64 * PAD;      // [c][r]

    const int qt = blockIdx.x;
    const int h  = blockIdx.y;
    const int b  = blockIdx.z;
    const int tid = threadIdx.x;
    const int tx = tid & 15;
    const int ty = tid >> 4;
    const int r0 = ty * 4;
    const int c0 = tx * 4;

    const int valid = g_valid[b];
    const int nkt = (valid > 0) ? ((valid + BKT - 1) / BKT) : (SLK / BKT);

    const float* Qb = g_q + ((size_t)b * SLQ + qt * BQ) * DMODEL + h * DHEAD;
    const float* Kb = g_k + (size_t)b * SLK * DMODEL + h * DHEAD;
    const float* Vb = g_v + (size_t)b * SLK * DMODEL + h * DHEAD;

    // load Q tile (transposed: Qs[d][r])
#pragma unroll
    for (int it = 0; it < (BQ * DHEAD) / 256; it++) {
        int idx = tid + it * 256;
        int r = idx >> 6, d = idx & 63;
        Qs[d * PAD + r] = Qb[(size_t)r * DMODEL + d];
    }

    float m[4], l[4], o[4][4];
#pragma unroll
    for (int i = 0; i < 4; i++) {
        m[i] = -1e30f; l[i] = 0.0f;
#pragma unroll
        for (int j = 0; j < 4; j++) o[i][j] = 0.0f;
    }

    for (int kt = 0; kt < nkt; kt++) {
        __syncthreads();   // previous iteration's PV reads done
#pragma unroll
        for (int it = 0; it < (BKT * DHEAD) / 256; it++) {
            int idx = tid + it * 256;
            int c = idx >> 6, d = idx & 63;
            float kvk = Kb[(size_t)(kt * BKT + c) * DMODEL + d];
            float kvv = Vb[(size_t)(kt * BKT + c) * DMODEL + d];
            Ks[d * PAD + c] = kvk;
            Vs[c * PAD + d] = kvv;
        }
        __syncthreads();

        // S = Q K^T
        float s[4][4];
#pragma unroll
        for (int i = 0; i < 4; i++)
#pragma unroll
            for (int j = 0; j < 4; j++) s[i][j] = 0.0f;

#pragma unroll 8
        for (int d = 0; d < 64; d++) {
            float4 a  = *(const float4*)&Qs[d * PAD + r0];
            float4 bb = *(const float4*)&Ks[d * PAD + c0];
            float av[4] = {a.x, a.y, a.z, a.w};
            float bv[4] = {bb.x, bb.y, bb.z, bb.w};
#pragma unroll
            for (int i = 0; i < 4; i++)
#pragma unroll
                for (int j = 0; j < 4; j++)
                    s[i][j] += av[i] * bv[j];
        }

        const float scale = 0.125f;   // 1/sqrt(64)
        const int kg0 = kt * BKT + c0;
#pragma unroll
        for (int i = 0; i < 4; i++)
#pragma unroll
            for (int j = 0; j < 4; j++) {
                float v = s[i][j] * scale;
                if (kg0 + j >= valid) v = -1e6f;
                s[i][j] = v;
            }

        // online softmax per row (rows live in 16 contiguous lanes)
#pragma unroll
        for (int i = 0; i < 4; i++) {
            float tm = fmaxf(fmaxf(s[i][0], s[i][1]), fmaxf(s[i][2], s[i][3]));
#pragma unroll
            for (int off = 1; off < 16; off <<= 1)
                tm = fmaxf(tm, __shfl_xor_sync(0xffffffffu, tm, off));
            float mn = fmaxf(m[i], tm);
            float corr = __expf(m[i] - mn);
            float p[4];
            float ts = 0.0f;
#pragma unroll
            for (int j = 0; j < 4; j++) { p[j] = __expf(s[i][j] - mn); ts += p[j]; }
#pragma unroll
            for (int off = 1; off < 16; off <<= 1)
                ts += __shfl_xor_sync(0xffffffffu, ts, off);
            l[i] = l[i] * corr + ts;
            m[i] = mn;
#pragma unroll
            for (int j = 0; j < 4; j++) o[i][j] *= corr;
#pragma unroll
            for (int j = 0; j < 4; j++) Ps[(c0 + j) * PAD + (r0 + i)] = p[j];
        }
        __syncthreads();

        // O += P V
#pragma unroll 8
        for (int c = 0; c < 64; c++) {
            float4 pv = *(const float4*)&Ps[c * PAD + r0];
            float4 vv = *(const float4*)&Vs[c * PAD + c0];
            float pa[4] = {pv.x, pv.y, pv.z, pv.w};
            float vb2[4] = {vv.x, vv.y, vv.z, vv.w};
#pragma unroll
            for (int i = 0; i < 4; i++)
#pragma unroll
                for (int j = 0; j < 4; j++)
                    o[i][j] += pa[i] * vb2[j];
        }
    }

    float* Ob = g_att + ((size_t)b * SLQ + qt * BQ) * DMODEL + h * DHEAD;
#pragma unroll
    for (int i = 0; i < 4; i++) {
        float inv = 1.0f / l[i];
#pragma unroll
        for (int j = 0; j < 4; j++)
            Ob[(size_t)(r0 + i) * DMODEL + c0 + j] = o[i][j] * inv;
    }
}

// ---------------------------------------------------------------------------
// LayerNorm over g_y rows -> out
// ---------------------------------------------------------------------------
__global__ __launch_bounds__(256)
void ln_kernel(const float* __restrict__ gamma,
               const float* __restrict__ beta,
               float* __restrict__ out)
{
    __shared__ float rs[256], rs2[256];
    const int row = blockIdx.x;
    const float* y = g_y + (size_t)row * DMODEL;
    float v[3], s = 0.0f, s2 = 0.0f;
#pragma unroll
    for (int t = 0; t < 3; t++) {
        v[t] = y[threadIdx.x + t * 256];
        s += v[t]; s2 += v[t] * v[t];
    }
    rs[threadIdx.x] = s; rs2[threadIdx.x] = s2;
    __syncthreads();
    for (int st = 128; st > 0; st >>= 1) {
        if (threadIdx.x < st) {
            rs[threadIdx.x]  += rs[threadIdx.x + st];
            rs2[threadIdx.x] += rs2[threadIdx.x + st];
        }
        __syncthreads();
    }
    const float mean = rs[0] * (1.0f / DMODEL);
    const float var  = rs2[0] * (1.0f / DMODEL) - mean * mean;
    const float inv  = rsqrtf(var + 1e-5f);
#pragma unroll
    for (int t = 0; t < 3; t++) {
        int col = threadIdx.x + t * 256;
        out[(size_t)row * DMODEL + col] = (v[t] - mean) * inv * gamma[col] + beta[col];
    }
}

// ---------------------------------------------------------------------------
// Launch
// ---------------------------------------------------------------------------
extern "C" void kernel_launch(void* const* d_in, const int* in_sizes, int n_in,
                              void* d_out, int out_size)
{
    (void)in_sizes; (void)n_in; (void)out_size;
    const float* queries = (const float*)d_in[0];
    const float* keys    = (const float*)d_in[1];
    const float* values  = (const float*)d_in[2];
    const int*   mask    = (const int*)  d_in[3];
    const float* Wq = (const float*)d_in[4];
    const float* Wk = (const float*)d_in[5];
    const float* Wv = (const float*)d_in[6];
    const float* Wo = (const float*)d_in[7];
    const float* W1 = (const float*)d_in[8];
    const float* b1 = (const float*)d_in[9];
    const float* W2 = (const float*)d_in[10];
    const float* b2 = (const float*)d_in[11];
    const float* lg = (const float*)d_in[12];
    const float* lb = (const float*)d_in[13];
    float* out = (float*)d_out;

    valid_kernel<<<BATCH, 256>>>(mask);

    dim3 ggrid(GN / 128, MROWS / 128);   // (6, 64)
    tgemm_kernel<0, 0, 0><<<ggrid, 256>>>(queries, Wq, nullptr);
    tgemm_kernel<0, 1, 0><<<ggrid, 256>>>(keys,    Wk, nullptr);
    tgemm_kernel<0, 2, 0><<<ggrid, 256>>>(values,  Wv, nullptr);

    cudaFuncSetAttribute(attn_kernel,
                         cudaFuncAttributeMaxDynamicSharedMemorySize,
                         (int)ATTN_SMEM);
    attn_kernel<<<dim3(SLQ / BQ, NHEAD, BATCH), 256, ATTN_SMEM>>>();

    tgemm_kernel<1, 3, 0><<<ggrid, 256>>>(nullptr, Wo, nullptr);  // att_out
    tgemm_kernel<2, 4, 1><<<ggrid, 256>>>(nullptr, W1, b1);       // relu(ffn1)
    tgemm_kernel<3, 5, 2><<<ggrid, 256>>>(nullptr, W2, b2);       // y = ffn2 + att_out

    ln_kernel<<<MROWS, 256>>>(lg, lb, out);
}

// round 8
// speedup vs baseline: 2.7635x; 1.6561x over previous
#include <cuda_runtime.h>
#include <math.h>

// Problem constants
#define BATCH  4
#define SLQ    2048
#define SLK    2048
#define DMODEL 768
#define NHEAD  12
#define DHEAD  64
#define MROWS  (BATCH * SLQ)   // 8192

// ---------------------------------------------------------------------------
// Scratch (device globals; no allocation allowed)
// ---------------------------------------------------------------------------
__device__ float g_q  [(size_t)MROWS * DMODEL];
__device__ float g_k  [(size_t)BATCH * SLK * DMODEL];
__device__ float g_v  [(size_t)BATCH * SLK * DMODEL];
__device__ float g_att[(size_t)MROWS * DMODEL];
__device__ float g_ao [(size_t)MROWS * DMODEL];
__device__ float g_f1 [(size_t)MROWS * DMODEL];
__device__ float g_y  [(size_t)MROWS * DMODEL];
__device__ int   g_valid[BATCH];

// ---------------------------------------------------------------------------
// valid_lens[b] = count of nonzero mask entries in row b
// ---------------------------------------------------------------------------
__global__ void valid_kernel(const int* __restrict__ mask) {
    __shared__ int red[256];
    int b = blockIdx.x;
    int cnt = 0;
    for (int i = threadIdx.x; i < SLK; i += 256)
        cnt += (mask[b * SLK + i] != 0) ? 1 : 0;
    red[threadIdx.x] = cnt;
    __syncthreads();
    for (int s = 128; s > 0; s >>= 1) {
        if (threadIdx.x < s) red[threadIdx.x] += red[threadIdx.x + s];
        __syncthreads();
    }
    if (threadIdx.x == 0) g_valid[b] = red[0];
}

// ---------------------------------------------------------------------------
// TF32 mma helpers
// ---------------------------------------------------------------------------
__device__ __forceinline__ unsigned f2tf(float f) {
    unsigned u;
    asm("cvt.rna.tf32.f32 %0, %1;" : "=r"(u) : "f"(f));
    return u;
}

__device__ __forceinline__ void mma_tf32(float c[4],
                                         const unsigned a[4],
                                         const unsigned b[2]) {
    asm volatile(
        "mma.sync.aligned.m16n8k8.row.col.f32.tf32.tf32.f32 "
        "{%0,%1,%2,%3}, {%4,%5,%6,%7}, {%8,%9}, {%0,%1,%2,%3};"
        : "+f"(c[0]), "+f"(c[1]), "+f"(c[2]), "+f"(c[3])
        : "r"(a[0]), "r"(a[1]), "r"(a[2]), "r"(a[3]),
          "r"(b[0]), "r"(b[1]));
}

// ---------------------------------------------------------------------------
// TF32 tensor-core GEMM: C[M,N] = A[M,K] @ B[K,N]  (M=8192, N=K=768)
// 128x128 block tile, BK=16 double-buffered, 8 warps, warp tile 32x64.
// ---------------------------------------------------------------------------
#define GK DMODEL
#define GN DMODEL
#define ASTRIDE 20
#define BSTRIDE 136

template<int ASEL, int CSEL, int MODE>
__global__ __launch_bounds__(256)
void tgemm_kernel(const float* __restrict__ Aext,
                  const float* __restrict__ Bm,
                  const float* __restrict__ bias)
{
    const float* A = (ASEL == 0) ? Aext : (ASEL == 1) ? g_att
                   : (ASEL == 2) ? g_ao : g_f1;
    float* C = (CSEL == 0) ? g_q : (CSEL == 1) ? g_k : (CSEL == 2) ? g_v
             : (CSEL == 3) ? g_ao : (CSEL == 4) ? g_f1 : g_y;

    __shared__ unsigned As[2][128 * ASTRIDE];
    __shared__ unsigned Bs[2][16 * BSTRIDE];

    const int bx = blockIdx.x;
    const int by = blockIdx.y;
    const int tid = threadIdx.x;
    const int warp = tid >> 5;
    const int lane = tid & 31;
    const int wm = warp >> 1;
    const int wn = warp & 1;
    const int g  = lane >> 2;
    const int t  = lane & 3;

    float acc[2][8][4];
#pragma unroll
    for (int mi = 0; mi < 2; mi++)
#pragma unroll
        for (int nj = 0; nj < 8; nj++)
#pragma unroll
            for (int q = 0; q < 4; q++) acc[mi][nj][q] = 0.0f;

    const int arow = tid >> 1;
    const int akc  = (tid & 1) * 8;
    const int bkr  = tid >> 4;
    const int bcol = (tid & 15) * 8;

    const float* Ag = A  + (size_t)(by * 128 + arow) * GK + akc;
    const float* Bg = Bm + (size_t)bkr * GN + bx * 128 + bcol;

    float4 pa0, pa1, pb0, pb1;

    pa0 = *(const float4*)(Ag);
    pa1 = *(const float4*)(Ag + 4);
    pb0 = *(const float4*)(Bg);
    pb1 = *(const float4*)(Bg + 4);
    {
        unsigned* as = &As[0][arow * ASTRIDE + akc];
        *(uint4*)as       = make_uint4(f2tf(pa0.x), f2tf(pa0.y), f2tf(pa0.z), f2tf(pa0.w));
        *(uint4*)(as + 4) = make_uint4(f2tf(pa1.x), f2tf(pa1.y), f2tf(pa1.z), f2tf(pa1.w));
        unsigned* bs = &Bs[0][bkr * BSTRIDE + bcol];
        *(uint4*)bs       = make_uint4(f2tf(pb0.x), f2tf(pb0.y), f2tf(pb0.z), f2tf(pb0.w));
        *(uint4*)(bs + 4) = make_uint4(f2tf(pb1.x), f2tf(pb1.y), f2tf(pb1.z), f2tf(pb1.w));
    }
    __syncthreads();

    const int NKT = GK / 16;
    int cur = 0;
#pragma unroll 1
    for (int kt = 0; kt < NKT; kt++) {
        if (kt + 1 < NKT) {
            const float* ag = Ag + (kt + 1) * 16;
            const float* bg = Bg + (size_t)(kt + 1) * 16 * GN;
            pa0 = *(const float4*)(ag);
            pa1 = *(const float4*)(ag + 4);
            pb0 = *(const float4*)(bg);
            pb1 = *(const float4*)(bg + 4);
        }

#pragma unroll
        for (int kk = 0; kk < 16; kk += 8) {
            unsigned af[2][4], bf[8][2];
#pragma unroll
            for (int mi = 0; mi < 2; mi++) {
                const int r = wm * 32 + mi * 16 + g;
                const unsigned* base = &As[cur][r * ASTRIDE + kk + t];
                af[mi][0] = base[0];
                af[mi][1] = base[8 * ASTRIDE];
                af[mi][2] = base[4];
                af[mi][3] = base[8 * ASTRIDE + 4];
            }
#pragma unroll
            for (int nj = 0; nj < 8; nj++) {
                const int c = wn * 64 + nj * 8 + g;
                bf[nj][0] = Bs[cur][(kk + t)     * BSTRIDE + c];
                bf[nj][1] = Bs[cur][(kk + t + 4) * BSTRIDE + c];
            }
#pragma unroll
            for (int mi = 0; mi < 2; mi++)
#pragma unroll
                for (int nj = 0; nj < 8; nj++)
                    mma_tf32(acc[mi][nj], af[mi], bf[nj]);
        }

        if (kt + 1 < NKT) {
            const int nxt = cur ^ 1;
            unsigned* as = &As[nxt][arow * ASTRIDE + akc];
            *(uint4*)as       = make_uint4(f2tf(pa0.x), f2tf(pa0.y), f2tf(pa0.z), f2tf(pa0.w));
            *(uint4*)(as + 4) = make_uint4(f2tf(pa1.x), f2tf(pa1.y), f2tf(pa1.z), f2tf(pa1.w));
            unsigned* bs = &Bs[nxt][bkr * BSTRIDE + bcol];
            *(uint4*)bs       = make_uint4(f2tf(pb0.x), f2tf(pb0.y), f2tf(pb0.z), f2tf(pb0.w));
            *(uint4*)(bs + 4) = make_uint4(f2tf(pb1.x), f2tf(pb1.y), f2tf(pb1.z), f2tf(pb1.w));
            __syncthreads();
            cur = nxt;
        }
    }

    const int row0 = by * 128 + wm * 32;
    const int col0 = bx * 128 + wn * 64;
#pragma unroll
    for (int mi = 0; mi < 2; mi++) {
#pragma unroll
        for (int nj = 0; nj < 8; nj++) {
            const int r = row0 + mi * 16 + g;
            const int c = col0 + nj * 8 + t * 2;
            float v0 = acc[mi][nj][0], v1 = acc[mi][nj][1];
            float v2 = acc[mi][nj][2], v3 = acc[mi][nj][3];
            if (MODE >= 1) {
                const float bb0 = bias[c], bb1 = bias[c + 1];
                v0 += bb0; v1 += bb1; v2 += bb0; v3 += bb1;
            }
            if (MODE == 1) {
                v0 = fmaxf(v0, 0.0f); v1 = fmaxf(v1, 0.0f);
                v2 = fmaxf(v2, 0.0f); v3 = fmaxf(v3, 0.0f);
            }
            if (MODE == 2) {
                const float* rr0 = g_ao + (size_t)r * GN + c;
                const float* rr1 = g_ao + (size_t)(r + 8) * GN + c;
                v0 += rr0[0]; v1 += rr0[1];
                v2 += rr1[0]; v3 += rr1[1];
            }
            *(float2*)(C + (size_t)r * GN + c)       = make_float2(v0, v1);
            *(float2*)(C + (size_t)(r + 8) * GN + c) = make_float2(v2, v3);
        }
    }
}

// ---------------------------------------------------------------------------
// Tensor-core flash attention.
// Block = (128 q rows, head h, batch b); 8 warps, each warp owns 16 q rows.
// K tile 64. QK^T and PV via mma.m16n8k8 tf32; online softmax in registers
// (quad shfl reductions). P staged per-warp through smem (C->A frag relayout).
// K tiles fully beyond valid_len skipped (exact).
// ---------------------------------------------------------------------------
#define BQ   128
#define BKT  64
#define QSTR 68
#define KSTR 68
#define VSTR 72
#define PSTR 68
#define ATTN_SMEM ((BQ*QSTR + BKT*KSTR + BKT*VSTR + BQ*PSTR) * 4)  // 105472 B

__global__ __launch_bounds__(256)
void attn_kernel() {
    extern __shared__ unsigned smu[];
    unsigned* Qs = smu;                    // [q][d]   stride 68
    unsigned* Ks = Qs + BQ * QSTR;         // [c][d]   stride 68 (natural)
    unsigned* Vs = Ks + BKT * KSTR;        // [c][d]   stride 72 (natural)
    unsigned* Ps = Vs + BKT * VSTR;        // per-warp [16][64] stride 68

    const int qt = blockIdx.x;
    const int h  = blockIdx.y;
    const int b  = blockIdx.z;
    const int tid  = threadIdx.x;
    const int warp = tid >> 5;
    const int lane = tid & 31;
    const int g = lane >> 2;
    const int t = lane & 3;
    const int R0 = warp * 16;
    unsigned* Pw = Ps + R0 * PSTR;

    const int valid = g_valid[b];
    const int nkt = (valid > 0) ? ((valid + BKT - 1) / BKT) : (SLK / BKT);

    const float* Qb = g_q + ((size_t)b * SLQ + qt * BQ) * DMODEL + h * DHEAD;
    const float* Kb = g_k + (size_t)b * SLK * DMODEL + h * DHEAD;
    const float* Vb = g_v + (size_t)b * SLK * DMODEL + h * DHEAD;

    // load Q tile (scaled by 1/sqrt(DH), tf32-converted)
#pragma unroll
    for (int it = 0; it < (BQ * 16) / 256; it++) {       // 8 iters
        int idx = it * 256 + tid;
        int r = idx >> 4, q4 = idx & 15;
        float4 v = *(const float4*)(Qb + (size_t)r * DMODEL + q4 * 4);
        unsigned* dst = &Qs[r * QSTR + q4 * 4];
        *(uint4*)dst = make_uint4(f2tf(v.x * 0.125f), f2tf(v.y * 0.125f),
                                  f2tf(v.z * 0.125f), f2tf(v.w * 0.125f));
    }

    float m_lo = -1e30f, m_hi = -1e30f, l_lo = 0.0f, l_hi = 0.0f;
    float oa[8][4];
#pragma unroll
    for (int nb = 0; nb < 8; nb++)
#pragma unroll
        for (int q = 0; q < 4; q++) oa[nb][q] = 0.0f;

#pragma unroll 1
    for (int kt = 0; kt < nkt; kt++) {
        __syncthreads();   // prev-tile K/V reads complete (also covers Q init)

        // load K & V tiles (natural [c][d] layout, tf32-converted)
#pragma unroll
        for (int it = 0; it < (BKT * 16) / 256; it++) {   // 4 iters
            int idx = it * 256 + tid;
            int c = idx >> 4, q4 = idx & 15;
            const float* src = (size_t)(kt * BKT + c) * DMODEL + q4 * 4 + Kb;
            float4 kv = *(const float4*)src;
            float4 vv = *(const float4*)(src + ((size_t)Vb - (size_t)Kb) / 4);
            *(uint4*)&Ks[c * KSTR + q4 * 4] =
                make_uint4(f2tf(kv.x), f2tf(kv.y), f2tf(kv.z), f2tf(kv.w));
            *(uint4*)&Vs[c * VSTR + q4 * 4] =
                make_uint4(f2tf(vv.x), f2tf(vv.y), f2tf(vv.z), f2tf(vv.w));
        }
        __syncthreads();

        // S = Q K^T  (64 mmas per warp)
        float sa[8][4];
#pragma unroll
        for (int nb = 0; nb < 8; nb++)
#pragma unroll
            for (int q = 0; q < 4; q++) sa[nb][q] = 0.0f;

#pragma unroll
        for (int kb = 0; kb < 8; kb++) {
            unsigned af[4];
            const unsigned* qp = &Qs[(R0 + g) * QSTR + kb * 8 + t];
            af[0] = qp[0];
            af[1] = qp[8 * QSTR];
            af[2] = qp[4];
            af[3] = qp[8 * QSTR + 4];
#pragma unroll
            for (int nb = 0; nb < 8; nb++) {
                unsigned bf[2];
                const unsigned* kp = &Ks[(nb * 8 + g) * KSTR + kb * 8 + t];
                bf[0] = kp[0];
                bf[1] = kp[4];
                mma_tf32(sa[nb], af, bf);
            }
        }

        // mask columns >= valid
        const int cbase = kt * BKT + 2 * t;
#pragma unroll
        for (int nb = 0; nb < 8; nb++) {
            const int c0 = cbase + nb * 8;
            if (c0     >= valid) { sa[nb][0] = -1e6f; sa[nb][2] = -1e6f; }
            if (c0 + 1 >= valid) { sa[nb][1] = -1e6f; sa[nb][3] = -1e6f; }
        }

        // online softmax (rows g and g+8 of this warp's 16)
        float tm_lo = -1e30f, tm_hi = -1e30f;
#pragma unroll
        for (int nb = 0; nb < 8; nb++) {
            tm_lo = fmaxf(tm_lo, fmaxf(sa[nb][0], sa[nb][1]));
            tm_hi = fmaxf(tm_hi, fmaxf(sa[nb][2], sa[nb][3]));
        }
#pragma unroll
        for (int off = 1; off < 4; off <<= 1) {
            tm_lo = fmaxf(tm_lo, __shfl_xor_sync(0xffffffffu, tm_lo, off));
            tm_hi = fmaxf(tm_hi, __shfl_xor_sync(0xffffffffu, tm_hi, off));
        }
        const float mn_lo = fmaxf(m_lo, tm_lo);
        const float mn_hi = fmaxf(m_hi, tm_hi);
        const float corr_lo = __expf(m_lo - mn_lo);
        const float corr_hi = __expf(m_hi - mn_hi);
        m_lo = mn_lo; m_hi = mn_hi;

        float ts_lo = 0.0f, ts_hi = 0.0f;
#pragma unroll
        for (int nb = 0; nb < 8; nb++) {
            float p0 = __expf(sa[nb][0] - mn_lo);
            float p1 = __expf(sa[nb][1] - mn_lo);
            float p2 = __expf(sa[nb][2] - mn_hi);
            float p3 = __expf(sa[nb][3] - mn_hi);
            ts_lo += p0 + p1;
            ts_hi += p2 + p3;
            *(uint2*)&Pw[g * PSTR + nb * 8 + 2 * t] =
                make_uint2(f2tf(p0), f2tf(p1));
            *(uint2*)&Pw[(g + 8) * PSTR + nb * 8 + 2 * t] =
                make_uint2(f2tf(p2), f2tf(p3));
        }
#pragma unroll
        for (int off = 1; off < 4; off <<= 1) {
            ts_lo += __shfl_xor_sync(0xffffffffu, ts_lo, off);
            ts_hi += __shfl_xor_sync(0xffffffffu, ts_hi, off);
        }
        l_lo = l_lo * corr_lo + ts_lo;
        l_hi = l_hi * corr_hi + ts_hi;
#pragma unroll
        for (int nb = 0; nb < 8; nb++) {
            oa[nb][0] *= corr_lo; oa[nb][1] *= corr_lo;
            oa[nb][2] *= corr_hi; oa[nb][3] *= corr_hi;
        }
        __syncwarp();

        // O += P V  (64 mmas per warp)
#pragma unroll
        for (int kb = 0; kb < 8; kb++) {
            unsigned af[4];
            const unsigned* pp = &Pw[g * PSTR + kb * 8 + t];
            af[0] = pp[0];
            af[1] = pp[8 * PSTR];
            af[2] = pp[4];
            af[3] = pp[8 * PSTR + 4];
#pragma unroll
            for (int nb = 0; nb < 8; nb++) {
                unsigned bf[2];
                const unsigned* vp = &Vs[(kb * 8 + t) * VSTR + nb * 8 + g];
                bf[0] = vp[0];
                bf[1] = vp[4 * VSTR];
                mma_tf32(oa[nb], af, bf);
            }
        }
        __syncwarp();   // Pw reads done before next tile's softmax overwrites
    }

    // epilogue
    const float inv_lo = 1.0f / l_lo;
    const float inv_hi = 1.0f / l_hi;
    const int row_lo = qt * BQ + R0 + g;
    float* Ob = g_att + ((size_t)b * SLQ) * DMODEL + h * DHEAD;
#pragma unroll
    for (int nb = 0; nb < 8; nb++) {
        const int c = nb * 8 + 2 * t;
        *(float2*)(Ob + (size_t)row_lo * DMODEL + c) =
            make_float2(oa[nb][0] * inv_lo, oa[nb][1] * inv_lo);
        *(float2*)(Ob + (size_t)(row_lo + 8) * DMODEL + c) =
            make_float2(oa[nb][2] * inv_hi, oa[nb][3] * inv_hi);
    }
}

// ---------------------------------------------------------------------------
// LayerNorm over g_y rows -> out
// ---------------------------------------------------------------------------
__global__ __launch_bounds__(256)
void ln_kernel(const float* __restrict__ gamma,
               const float* __restrict__ beta,
               float* __restrict__ out)
{
    __shared__ float rs[256], rs2[256];
    const int row = blockIdx.x;
    const float* y = g_y + (size_t)row * DMODEL;
    float v[3], s = 0.0f, s2 = 0.0f;
#pragma unroll
    for (int t = 0; t < 3; t++) {
        v[t] = y[threadIdx.x + t * 256];
        s += v[t]; s2 += v[t] * v[t];
    }
    rs[threadIdx.x] = s; rs2[threadIdx.x] = s2;
    __syncthreads();
    for (int st = 128; st > 0; st >>= 1) {
        if (threadIdx.x < st) {
            rs[threadIdx.x]  += rs[threadIdx.x + st];
            rs2[threadIdx.x] += rs2[threadIdx.x + st];
        }
        __syncthreads();
    }
    const float mean = rs[0] * (1.0f / DMODEL);
    const float var  = rs2[0] * (1.0f / DMODEL) - mean * mean;
    const float inv  = rsqrtf(var + 1e-5f);
#pragma unroll
    for (int t = 0; t < 3; t++) {
        int col = threadIdx.x + t * 256;
        out[(size_t)row * DMODEL + col] = (v[t] - mean) * inv * gamma[col] + beta[col];
    }
}

// ---------------------------------------------------------------------------
// Launch
// ---------------------------------------------------------------------------
extern "C" void kernel_launch(void* const* d_in, const int* in_sizes, int n_in,
                              void* d_out, int out_size)
{
    (void)in_sizes; (void)n_in; (void)out_size;
    const float* queries = (const float*)d_in[0];
    const float* keys    = (const float*)d_in[1];
    const float* values  = (const float*)d_in[2];
    const int*   mask    = (const int*)  d_in[3];
    const float* Wq = (const float*)d_in[4];
    const float* Wk = (const float*)d_in[5];
    const float* Wv = (const float*)d_in[6];
    const float* Wo = (const float*)d_in[7];
    const float* W1 = (const float*)d_in[8];
    const float* b1 = (const float*)d_in[9];
    const float* W2 = (const float*)d_in[10];
    const float* b2 = (const float*)d_in[11];
    const float* lg = (const float*)d_in[12];
    const float* lb = (const float*)d_in[13];
    float* out = (float*)d_out;

    valid_kernel<<<BATCH, 256>>>(mask);

    dim3 ggrid(GN / 128, MROWS / 128);   // (6, 64)
    tgemm_kernel<0, 0, 0><<<ggrid, 256>>>(queries, Wq, nullptr);
    tgemm_kernel<0, 1, 0><<<ggrid, 256>>>(keys,    Wk, nullptr);
    tgemm_kernel<0, 2, 0><<<ggrid, 256>>>(values,  Wv, nullptr);

    cudaFuncSetAttribute(attn_kernel,
                         cudaFuncAttributeMaxDynamicSharedMemorySize,
                         (int)ATTN_SMEM);
    attn_kernel<<<dim3(SLQ / BQ, NHEAD, BATCH), 256, ATTN_SMEM>>>();

    tgemm_kernel<1, 3, 0><<<ggrid, 256>>>(nullptr, Wo, nullptr);  // att_out
    tgemm_kernel<2, 4, 1><<<ggrid, 256>>>(nullptr, W1, b1);       // relu(ffn1)
    tgemm_kernel<3, 5, 2><<<ggrid, 256>>>(nullptr, W2, b2);       // y = ffn2 + att_out

    ln_kernel<<<MROWS, 256>>>(lg, lb, out);
}

// round 9
// speedup vs baseline: 2.8522x; 1.0321x over previous
#include <cuda_runtime.h>
#include <math.h>

// Problem constants
#define BATCH  4
#define SLQ    2048
#define SLK    2048
#define DMODEL 768
#define NHEAD  12
#define DHEAD  64
#define MROWS  (BATCH * SLQ)   // 8192

// ---------------------------------------------------------------------------
// Scratch (device globals; no allocation allowed)
// ---------------------------------------------------------------------------
__device__ float g_q  [(size_t)MROWS * DMODEL];
__device__ float g_k  [(size_t)BATCH * SLK * DMODEL];
__device__ float g_v  [(size_t)BATCH * SLK * DMODEL];
__device__ float g_att[(size_t)MROWS * DMODEL];
__device__ float g_ao [(size_t)MROWS * DMODEL];
__device__ float g_f1 [(size_t)MROWS * DMODEL];
__device__ float g_y  [(size_t)MROWS * DMODEL];
__device__ int   g_valid[BATCH];

// ---------------------------------------------------------------------------
// valid_lens[b] = count of nonzero mask entries in row b
// ---------------------------------------------------------------------------
__global__ void valid_kernel(const int* __restrict__ mask) {
    __shared__ int red[256];
    int b = blockIdx.x;
    int cnt = 0;
    for (int i = threadIdx.x; i < SLK; i += 256)
        cnt += (mask[b * SLK + i] != 0) ? 1 : 0;
    red[threadIdx.x] = cnt;
    __syncthreads();
    for (int s = 128; s > 0; s >>= 1) {
        if (threadIdx.x < s) red[threadIdx.x] += red[threadIdx.x + s];
        __syncthreads();
    }
    if (threadIdx.x == 0) g_valid[b] = red[0];
}

// ---------------------------------------------------------------------------
// TF32 mma helpers
// ---------------------------------------------------------------------------
__device__ __forceinline__ unsigned f2tf(float f) {
    unsigned u;
    asm("cvt.rna.tf32.f32 %0, %1;" : "=r"(u) : "f"(f));
    return u;
}

__device__ __forceinline__ void mma_tf32(float c[4],
                                         const unsigned a[4],
                                         const unsigned b[2]) {
    asm volatile(
        "mma.sync.aligned.m16n8k8.row.col.f32.tf32.tf32.f32 "
        "{%0,%1,%2,%3}, {%4,%5,%6,%7}, {%8,%9}, {%0,%1,%2,%3};"
        : "+f"(c[0]), "+f"(c[1]), "+f"(c[2]), "+f"(c[3])
        : "r"(a[0]), "r"(a[1]), "r"(a[2]), "r"(a[3]),
          "r"(b[0]), "r"(b[1]));
}

// ---------------------------------------------------------------------------
// TF32 tensor-core GEMM: C[M,N] = A[M,K] @ B[K,N]  (M=8192, N=K=768)
// 128x128 block tile, BK=16 double-buffered, 8 warps, warp tile 32x64.
// A smem: per-row k-interleaved pairs (k, k+4), stride 24 -> a-frag LDS.64.
// B smem: [kchunk][t][n][pair] (pair = k, k+4), t-row stride 264 -> b LDS.64.
// ---------------------------------------------------------------------------
#define GK DMODEL
#define GN DMODEL
#define ASTR 24      // 16 data + 8 pad (== 24 mod 32 -> conflict-free frags)
#define BTR  264     // 256 data + 8 pad (== 8 mod 32 -> conflict-free frags)
#define BCH  (4 * BTR)   // 1056 (one k-chunk: 4 t-rows)

template<int ASEL, int CSEL, int MODE>
__global__ __launch_bounds__(256, 2)
void tgemm_kernel(const float* __restrict__ Aext,
                  const float* __restrict__ Bm,
                  const float* __restrict__ bias)
{
    const float* A = (ASEL == 0) ? Aext : (ASEL == 1) ? g_att
                   : (ASEL == 2) ? g_ao : g_f1;
    float* C = (CSEL == 0) ? g_q : (CSEL == 1) ? g_k : (CSEL == 2) ? g_v
             : (CSEL == 3) ? g_ao : (CSEL == 4) ? g_f1 : g_y;

    __shared__ unsigned As[2][128 * ASTR];   // 24.6 KB
    __shared__ unsigned Bs[2][2 * BCH];      // 16.9 KB

    const int bx = blockIdx.x;
    const int by = blockIdx.y;
    const int tid = threadIdx.x;
    const int warp = tid >> 5;
    const int lane = tid & 31;
    const int wm = warp >> 1;
    const int wn = warp & 1;
    const int g  = lane >> 2;
    const int t  = lane & 3;

    float acc[2][8][4];
#pragma unroll
    for (int mi = 0; mi < 2; mi++)
#pragma unroll
        for (int nj = 0; nj < 8; nj++)
#pragma unroll
            for (int q = 0; q < 4; q++) acc[mi][nj][q] = 0.0f;

    // A loader mapping: thread reads 8 consecutive k of one row
    const int arow = tid >> 1;
    const int akc  = (tid & 1) * 8;
    // B loader mapping: thread reads 4 n's at k rows (kkc*8+tb, +4)
    const int bn4  = (tid & 31) * 4;
    const int bkrw = tid >> 5;        // 0..7
    const int bkkc = bkrw >> 2;       // 0..1
    const int btb  = bkrw & 3;        // 0..3

    const float* Ag  = A  + (size_t)(by * 128 + arow) * GK + akc;
    const float* BgL = Bm + (size_t)(bkkc * 8 + btb) * GN + bx * 128 + bn4;
    const float* BgH = BgL + 4 * GN;

    float4 pa0, pa1, pb0, pb1;

    // prologue: load tile 0
    pa0 = *(const float4*)(Ag);
    pa1 = *(const float4*)(Ag + 4);
    pb0 = *(const float4*)(BgL);
    pb1 = *(const float4*)(BgH);
    {
        unsigned* as = &As[0][arow * ASTR + akc];
        *(uint4*)as       = make_uint4(f2tf(pa0.x), f2tf(pa1.x), f2tf(pa0.y), f2tf(pa1.y));
        *(uint4*)(as + 4) = make_uint4(f2tf(pa0.z), f2tf(pa1.z), f2tf(pa0.w), f2tf(pa1.w));
        unsigned* bs = &Bs[0][bkkc * BCH + btb * BTR + bn4 * 2];
        *(uint4*)bs       = make_uint4(f2tf(pb0.x), f2tf(pb1.x), f2tf(pb0.y), f2tf(pb1.y));
        *(uint4*)(bs + 4) = make_uint4(f2tf(pb0.z), f2tf(pb1.z), f2tf(pb0.w), f2tf(pb1.w));
    }
    __syncthreads();

    const int NKT = GK / 16;   // 48
    int cur = 0;
#pragma unroll 1
    for (int kt = 0; kt < NKT; kt++) {
        if (kt + 1 < NKT) {
            const float* ag = Ag + (kt + 1) * 16;
            const float* bl = BgL + (size_t)(kt + 1) * 16 * GN;
            pa0 = *(const float4*)(ag);
            pa1 = *(const float4*)(ag + 4);
            pb0 = *(const float4*)(bl);
            pb1 = *(const float4*)(bl + 4 * GN);
        }

#pragma unroll
        for (int kk = 0; kk < 16; kk += 8) {
            const int kkc = kk >> 3;
            unsigned af[2][4], bf[8][2];
#pragma unroll
            for (int mi = 0; mi < 2; mi++) {
                const int r = wm * 32 + mi * 16 + g;
                uint2 q0 = *(const uint2*)&As[cur][r * ASTR + kk + 2 * t];
                uint2 q1 = *(const uint2*)&As[cur][(r + 8) * ASTR + kk + 2 * t];
                af[mi][0] = q0.x; af[mi][1] = q1.x;
                af[mi][2] = q0.y; af[mi][3] = q1.y;
            }
#pragma unroll
            for (int nj = 0; nj < 8; nj++) {
                const int c = wn * 64 + nj * 8 + g;
                uint2 qb = *(const uint2*)&Bs[cur][kkc * BCH + t * BTR + c * 2];
                bf[nj][0] = qb.x; bf[nj][1] = qb.y;
            }
#pragma unroll
            for (int mi = 0; mi < 2; mi++)
#pragma unroll
                for (int nj = 0; nj < 8; nj++)
                    mma_tf32(acc[mi][nj], af[mi], bf[nj]);
        }

        if (kt + 1 < NKT) {
            const int nxt = cur ^ 1;
            unsigned* as = &As[nxt][arow * ASTR + akc];
            *(uint4*)as       = make_uint4(f2tf(pa0.x), f2tf(pa1.x), f2tf(pa0.y), f2tf(pa1.y));
            *(uint4*)(as + 4) = make_uint4(f2tf(pa0.z), f2tf(pa1.z), f2tf(pa0.w), f2tf(pa1.w));
            unsigned* bs = &Bs[nxt][bkkc * BCH + btb * BTR + bn4 * 2];
            *(uint4*)bs       = make_uint4(f2tf(pb0.x), f2tf(pb1.x), f2tf(pb0.y), f2tf(pb1.y));
            *(uint4*)(bs + 4) = make_uint4(f2tf(pb0.z), f2tf(pb1.z), f2tf(pb0.w), f2tf(pb1.w));
            __syncthreads();
            cur = nxt;
        }
    }

    const int row0 = by * 128 + wm * 32;
    const int col0 = bx * 128 + wn * 64;
#pragma unroll
    for (int mi = 0; mi < 2; mi++) {
#pragma unroll
        for (int nj = 0; nj < 8; nj++) {
            const int r = row0 + mi * 16 + g;
            const int c = col0 + nj * 8 + t * 2;
            float v0 = acc[mi][nj][0], v1 = acc[mi][nj][1];
            float v2 = acc[mi][nj][2], v3 = acc[mi][nj][3];
            if (MODE >= 1) {
                const float bb0 = bias[c], bb1 = bias[c + 1];
                v0 += bb0; v1 += bb1; v2 += bb0; v3 += bb1;
            }
            if (MODE == 1) {
                v0 = fmaxf(v0, 0.0f); v1 = fmaxf(v1, 0.0f);
                v2 = fmaxf(v2, 0.0f); v3 = fmaxf(v3, 0.0f);
            }
            if (MODE == 2) {
                const float* rr0 = g_ao + (size_t)r * GN + c;
                const float* rr1 = g_ao + (size_t)(r + 8) * GN + c;
                v0 += rr0[0]; v1 += rr0[1];
                v2 += rr1[0]; v3 += rr1[1];
            }
            *(float2*)(C + (size_t)r * GN + c)       = make_float2(v0, v1);
            *(float2*)(C + (size_t)(r + 8) * GN + c) = make_float2(v2, v3);
        }
    }
}

// ---------------------------------------------------------------------------
// Tensor-core flash attention (tf32 mma).
// Block = (128 q rows, head h, batch b); 8 warps x 16 q rows.
// Q/K smem: per-row k-interleaved pairs, stride 72 -> LDS.64 frags.
// V smem: [kvchunk][t][d][pair], t-row stride 136 -> LDS.64 frags.
// P staged per-warp ([r][c], stride 68, scalar frag loads — relayout is a wash).
// K tiles fully beyond valid_len skipped (exact).
// ---------------------------------------------------------------------------
#define BQ   128
#define BKT  64
#define QSTR 72
#define KSTR 72
#define VTR  136
#define VCH  (4 * VTR)    // 544
#define PSTR 68
#define ATTN_SMEM ((BQ*QSTR + BKT*KSTR + 8*VCH + BQ*PSTR) * 4)  // 107520 B

__global__ __launch_bounds__(256)
void attn_kernel() {
    extern __shared__ unsigned smu[];
    unsigned* Qs = smu;                    // [q][d-interleaved] stride 72
    unsigned* Ks = Qs + BQ * QSTR;         // [c][d-interleaved] stride 72
    unsigned* Vs = Ks + BKT * KSTR;        // [kvc][t][d][pair]
    unsigned* Ps = Vs + 8 * VCH;           // per-warp [16][64] stride 68

    const int qt = blockIdx.x;
    const int h  = blockIdx.y;
    const int b  = blockIdx.z;
    const int tid  = threadIdx.x;
    const int warp = tid >> 5;
    const int lane = tid & 31;
    const int g = lane >> 2;
    const int t = lane & 3;
    const int R0 = warp * 16;
    unsigned* Pw = Ps + R0 * PSTR;

    const int valid = g_valid[b];
    const int nkt = (valid > 0) ? ((valid + BKT - 1) / BKT) : (SLK / BKT);

    const float* Qb = g_q + ((size_t)b * SLQ + qt * BQ) * DMODEL + h * DHEAD;
    const float* Kb = g_k + (size_t)b * SLK * DMODEL + h * DHEAD;
    const float* Vb = g_v + (size_t)b * SLK * DMODEL + h * DHEAD;

    // load Q tile: k-interleaved pairs, scaled by 1/8, tf32
#pragma unroll
    for (int it = 0; it < 4; it++) {
        int idx = it * 256 + tid;
        int r = idx >> 3, c8 = idx & 7;
        const float* p = Qb + (size_t)r * DMODEL + c8 * 8;
        float4 lo = *(const float4*)(p);
        float4 hi = *(const float4*)(p + 4);
        unsigned* q = &Qs[r * QSTR + c8 * 8];
        *(uint4*)q       = make_uint4(f2tf(lo.x * 0.125f), f2tf(hi.x * 0.125f),
                                      f2tf(lo.y * 0.125f), f2tf(hi.y * 0.125f));
        *(uint4*)(q + 4) = make_uint4(f2tf(lo.z * 0.125f), f2tf(hi.z * 0.125f),
                                      f2tf(lo.w * 0.125f), f2tf(hi.w * 0.125f));
    }

    float m_lo = -1e30f, m_hi = -1e30f, l_lo = 0.0f, l_hi = 0.0f;
    float oa[8][4];
#pragma unroll
    for (int nb = 0; nb < 8; nb++)
#pragma unroll
        for (int q = 0; q < 4; q++) oa[nb][q] = 0.0f;

    // V loader mapping
    const int vd8 = (tid & 7) * 8;
    const int vrp = tid >> 3;
    const int vkvc = vrp >> 2;
    const int vtt  = vrp & 3;

#pragma unroll 1
    for (int kt = 0; kt < nkt; kt++) {
        __syncthreads();   // prev-tile K/V reads complete (also covers Q init)

        // K tile: k-interleaved rows
#pragma unroll
        for (int it = 0; it < 2; it++) {
            int idx = it * 256 + tid;
            int r = idx >> 3, c8 = idx & 7;
            const float* p = Kb + (size_t)(kt * BKT + r) * DMODEL + c8 * 8;
            float4 lo = *(const float4*)(p);
            float4 hi = *(const float4*)(p + 4);
            unsigned* q = &Ks[r * KSTR + c8 * 8];
            *(uint4*)q       = make_uint4(f2tf(lo.x), f2tf(hi.x), f2tf(lo.y), f2tf(hi.y));
            *(uint4*)(q + 4) = make_uint4(f2tf(lo.z), f2tf(hi.z), f2tf(lo.w), f2tf(hi.w));
        }
        // V tile: [kvc][t][d][pair]; thread reads rows kv0, kv0+4
        {
            const float* p0 = Vb + (size_t)(kt * BKT + vkvc * 8 + vtt) * DMODEL + vd8;
            const float* p1 = p0 + 4 * DMODEL;
            float4 lo0 = *(const float4*)(p0);
            float4 lo1 = *(const float4*)(p0 + 4);
            float4 hi0 = *(const float4*)(p1);
            float4 hi1 = *(const float4*)(p1 + 4);
            unsigned* vdst = &Vs[vkvc * VCH + vtt * VTR + vd8 * 2];
            *(uint4*)(vdst)      = make_uint4(f2tf(lo0.x), f2tf(hi0.x), f2tf(lo0.y), f2tf(hi0.y));
            *(uint4*)(vdst + 4)  = make_uint4(f2tf(lo0.z), f2tf(hi0.z), f2tf(lo0.w), f2tf(hi0.w));
            *(uint4*)(vdst + 8)  = make_uint4(f2tf(lo1.x), f2tf(hi1.x), f2tf(lo1.y), f2tf(hi1.y));
            *(uint4*)(vdst + 12) = make_uint4(f2tf(lo1.z), f2tf(hi1.z), f2tf(lo1.w), f2tf(hi1.w));
        }
        __syncthreads();

        // S = Q K^T  (64 mmas per warp)
        float sa[8][4];
#pragma unroll
        for (int nb = 0; nb < 8; nb++)
#pragma unroll
            for (int q = 0; q < 4; q++) sa[nb][q] = 0.0f;

#pragma unroll
        for (int kb = 0; kb < 8; kb++) {
            unsigned af[4];
            uint2 q0 = *(const uint2*)&Qs[(R0 + g) * QSTR + kb * 8 + 2 * t];
            uint2 q1 = *(const uint2*)&Qs[(R0 + g + 8) * QSTR + kb * 8 + 2 * t];
            af[0] = q0.x; af[1] = q1.x; af[2] = q0.y; af[3] = q1.y;
#pragma unroll
            for (int nb = 0; nb < 8; nb++) {
                unsigned bf[2];
                uint2 qk = *(const uint2*)&Ks[(nb * 8 + g) * KSTR + kb * 8 + 2 * t];
                bf[0] = qk.x; bf[1] = qk.y;
                mma_tf32(sa[nb], af, bf);
            }
        }

        // mask columns >= valid
        const int cbase = kt * BKT + 2 * t;
#pragma unroll
        for (int nb = 0; nb < 8; nb++) {
            const int c0 = cbase + nb * 8;
            if (c0     >= valid) { sa[nb][0] = -1e6f; sa[nb][2] = -1e6f; }
            if (c0 + 1 >= valid) { sa[nb][1] = -1e6f; sa[nb][3] = -1e6f; }
        }

        // online softmax (rows g and g+8 of this warp's 16)
        float tm_lo = -1e30f, tm_hi = -1e30f;
#pragma unroll
        for (int nb = 0; nb < 8; nb++) {
            tm_lo = fmaxf(tm_lo, fmaxf(sa[nb][0], sa[nb][1]));
            tm_hi = fmaxf(tm_hi, fmaxf(sa[nb][2], sa[nb][3]));
        }
#pragma unroll
        for (int off = 1; off < 4; off <<= 1) {
            tm_lo = fmaxf(tm_lo, __shfl_xor_sync(0xffffffffu, tm_lo, off));
            tm_hi = fmaxf(tm_hi, __shfl_xor_sync(0xffffffffu, tm_hi, off));
        }
        const float mn_lo = fmaxf(m_lo, tm_lo);
        const float mn_hi = fmaxf(m_hi, tm_hi);
        const float corr_lo = __expf(m_lo - mn_lo);
        const float corr_hi = __expf(m_hi - mn_hi);
        m_lo = mn_lo; m_hi = mn_hi;

        float ts_lo = 0.0f, ts_hi = 0.0f;
#pragma unroll
        for (int nb = 0; nb < 8; nb++) {
            float p0 = __expf(sa[nb][0] - mn_lo);
            float p1 = __expf(sa[nb][1] - mn_lo);
            float p2 = __expf(sa[nb][2] - mn_hi);
            float p3 = __expf(sa[nb][3] - mn_hi);
            ts_lo += p0 + p1;
            ts_hi += p2 + p3;
            *(uint2*)&Pw[g * PSTR + nb * 8 + 2 * t] =
                make_uint2(f2tf(p0), f2tf(p1));
            *(uint2*)&Pw[(g + 8) * PSTR + nb * 8 + 2 * t] =
                make_uint2(f2tf(p2), f2tf(p3));
        }
#pragma unroll
        for (int off = 1; off < 4; off <<= 1) {
            ts_lo += __shfl_xor_sync(0xffffffffu, ts_lo, off);
            ts_hi += __shfl_xor_sync(0xffffffffu, ts_hi, off);
        }
        l_lo = l_lo * corr_lo + ts_lo;
        l_hi = l_hi * corr_hi + ts_hi;
#pragma unroll
        for (int nb = 0; nb < 8; nb++) {
            oa[nb][0] *= corr_lo; oa[nb][1] *= corr_lo;
            oa[nb][2] *= corr_hi; oa[nb][3] *= corr_hi;
        }
        __syncwarp();

        // O += P V  (64 mmas per warp)
#pragma unroll
        for (int kb = 0; kb < 8; kb++) {
            unsigned af[4];
            const unsigned* pp = &Pw[g * PSTR + kb * 8 + t];
            af[0] = pp[0];
            af[1] = pp[8 * PSTR];
            af[2] = pp[4];
            af[3] = pp[8 * PSTR + 4];
#pragma unroll
            for (int nb = 0; nb < 8; nb++) {
                unsigned bf[2];
                uint2 qv = *(const uint2*)&Vs[kb * VCH + t * VTR + (nb * 8 + g) * 2];
                bf[0] = qv.x; bf[1] = qv.y;
                mma_tf32(oa[nb], af, bf);
            }
        }
        __syncwarp();   // Pw reads done before next tile's softmax overwrites
    }

    // epilogue
    const float inv_lo = 1.0f / l_lo;
    const float inv_hi = 1.0f / l_hi;
    const int row_lo = qt * BQ + R0 + g;
    float* Ob = g_att + ((size_t)b * SLQ) * DMODEL + h * DHEAD;
#pragma unroll
    for (int nb = 0; nb < 8; nb++) {
        const int c = nb * 8 + 2 * t;
        *(float2*)(Ob + (size_t)row_lo * DMODEL + c) =
            make_float2(oa[nb][0] * inv_lo, oa[nb][1] * inv_lo);
        *(float2*)(Ob + (size_t)(row_lo + 8) * DMODEL + c) =
            make_float2(oa[nb][2] * inv_hi, oa[nb][3] * inv_hi);
    }
}

// ---------------------------------------------------------------------------
// LayerNorm over g_y rows -> out
// ---------------------------------------------------------------------------
__global__ __launch_bounds__(256)
void ln_kernel(const float* __restrict__ gamma,
               const float* __restrict__ beta,
               float* __restrict__ out)
{
    __shared__ float rs[256], rs2[256];
    const int row = blockIdx.x;
    const float* y = g_y + (size_t)row * DMODEL;
    float v[3], s = 0.0f, s2 = 0.0f;
#pragma unroll
    for (int t = 0; t < 3; t++) {
        v[t] = y[threadIdx.x + t * 256];
        s += v[t]; s2 += v[t] * v[t];
    }
    rs[threadIdx.x] = s; rs2[threadIdx.x] = s2;
    __syncthreads();
    for (int st = 128; st > 0; st >>= 1) {
        if (threadIdx.x < st) {
            rs[threadIdx.x]  += rs[threadIdx.x + st];
            rs2[threadIdx.x] += rs2[threadIdx.x + st];
        }
        __syncthreads();
    }
    const float mean = rs[0] * (1.0f / DMODEL);
    const float var  = rs2[0] * (1.0f / DMODEL) - mean * mean;
    const float inv  = rsqrtf(var + 1e-5f);
#pragma unroll
    for (int t = 0; t < 3; t++) {
        int col = threadIdx.x + t * 256;
        out[(size_t)row * DMODEL + col] = (v[t] - mean) * inv * gamma[col] + beta[col];
    }
}

// ---------------------------------------------------------------------------
// Launch
// ---------------------------------------------------------------------------
extern "C" void kernel_launch(void* const* d_in, const int* in_sizes, int n_in,
                              void* d_out, int out_size)
{
    (void)in_sizes; (void)n_in; (void)out_size;
    const float* queries = (const float*)d_in[0];
    const float* keys    = (const float*)d_in[1];
    const float* values  = (const float*)d_in[2];
    const int*   mask    = (const int*)  d_in[3];
    const float* Wq = (const float*)d_in[4];
    const float* Wk = (const float*)d_in[5];
    const float* Wv = (const float*)d_in[6];
    const float* Wo = (const float*)d_in[7];
    const float* W1 = (const float*)d_in[8];
    const float* b1 = (const float*)d_in[9];
    const float* W2 = (const float*)d_in[10];
    const float* b2 = (const float*)d_in[11];
    const float* lg = (const float*)d_in[12];
    const float* lb = (const float*)d_in[13];
    float* out = (float*)d_out;

    valid_kernel<<<BATCH, 256>>>(mask);

    dim3 ggrid(GN / 128, MROWS / 128);   // (6, 64)
    tgemm_kernel<0, 0, 0><<<ggrid, 256>>>(queries, Wq, nullptr);
    tgemm_kernel<0, 1, 0><<<ggrid, 256>>>(keys,    Wk, nullptr);
    tgemm_kernel<0, 2, 0><<<ggrid, 256>>>(values,  Wv, nullptr);

    cudaFuncSetAttribute(attn_kernel,
                         cudaFuncAttributeMaxDynamicSharedMemorySize,
                         (int)ATTN_SMEM);
    attn_kernel<<<dim3(SLQ / BQ, NHEAD, BATCH), 256, ATTN_SMEM>>>();

    tgemm_kernel<1, 3, 0><<<ggrid, 256>>>(nullptr, Wo, nullptr);  // att_out
    tgemm_kernel<2, 4, 1><<<ggrid, 256>>>(nullptr, W1, b1);       // relu(ffn1)
    tgemm_kernel<3, 5, 2><<<ggrid, 256>>>(nullptr, W2, b2);       // y = ffn2 + att_out

    ln_kernel<<<MROWS, 256>>>(lg, lb, out);
}